// round 7
// baseline (speedup 1.0000x reference)
#include <cuda_runtime.h>
#include <cuda_bf16.h>
#include <cstdint>

// Problem constants (fixed shapes for this problem)
#define N_NODES 50000
#define D_IN    128
#define D_FF    256
#define D_OUT   119

// Scratch (allocation-free rule: __device__ globals). 16B-aligned.
__device__ __align__(16) float g_h[(size_t)N_NODES * D_IN];        // 25.6 MB
__device__ __align__(16) float g_aggr[(size_t)N_NODES * D_IN];     // 25.6 MB
__device__ __align__(16) uint32_t g_Ahi[(size_t)N_NODES * (D_IN/2)];   // 12.8 MB
__device__ __align__(16) uint32_t g_Alo[(size_t)N_NODES * (D_IN/2)];   // 12.8 MB
__device__ __align__(16) uint32_t g_hidh[(size_t)N_NODES * (D_FF/2)];  // 25.6 MB
__device__ __align__(16) uint32_t g_hidl[(size_t)N_NODES * (D_FF/2)];  // 25.6 MB
__device__ unsigned g_maskbits[(N_NODES + 31) / 32];               // 6.25 KB

// ---------------------------------------------------------------------------
// MMA + ldmatrix primitives
// ---------------------------------------------------------------------------
__device__ __forceinline__ void mma16816(float* c, const uint32_t* a,
                                         uint32_t b0, uint32_t b1)
{
    asm volatile(
        "mma.sync.aligned.m16n8k16.row.col.f32.bf16.bf16.f32 "
        "{%0,%1,%2,%3}, {%4,%5,%6,%7}, {%8,%9}, {%0,%1,%2,%3};"
        : "+f"(c[0]), "+f"(c[1]), "+f"(c[2]), "+f"(c[3])
        : "r"(a[0]), "r"(a[1]), "r"(a[2]), "r"(a[3]), "r"(b0), "r"(b1));
}

__device__ __forceinline__ void ldsm4(uint32_t* r, const uint32_t* p)
{
    uint32_t a = (uint32_t)__cvta_generic_to_shared(p);
    asm volatile("ldmatrix.sync.aligned.m8n8.x4.shared.b16 {%0,%1,%2,%3}, [%4];"
                 : "=r"(r[0]), "=r"(r[1]), "=r"(r[2]), "=r"(r[3]) : "r"(a));
}

__device__ __forceinline__ void split_bf16(float x, __nv_bfloat16& hi, __nv_bfloat16& lo)
{
    hi = __float2bfloat16_rn(x);
    lo = __float2bfloat16_rn(x - __bfloat162float(hi));
}

// Convert a float4 into hi/lo bf16x2 pair words
__device__ __forceinline__ void cvt4(const float4& v, uint32_t& h0, uint32_t& h1,
                                     uint32_t& l0, uint32_t& l1)
{
    __nv_bfloat16 hx, lx, hy, ly, hz, lz, hw, lw;
    split_bf16(v.x, hx, lx); split_bf16(v.y, hy, ly);
    split_bf16(v.z, hz, lz); split_bf16(v.w, hw, lw);
    __nv_bfloat162 a = __nv_bfloat162(hx, hy), b = __nv_bfloat162(hz, hw);
    __nv_bfloat162 c = __nv_bfloat162(lx, ly), d = __nv_bfloat162(lz, lw);
    h0 = *(uint32_t*)&a; h1 = *(uint32_t*)&b;
    l0 = *(uint32_t*)&c; l1 = *(uint32_t*)&d;
}

// ---------------------------------------------------------------------------
// Shared GEMM geometry: BM=128, BN=64, BK=32; 256 threads; warp = 32x32 out.
// acc += Ah*Bh + Al*Bh + Ah*Bl  (fp32 accumulate)
// ---------------------------------------------------------------------------
#define BMg 128
#define BNg 64
#define ASP 20   /* smem stride in bf16 PAIRS (40 bf16 = 80B) */
#define BSP 20
#define SMEM_WORDS (4 * BMg * ASP + 4 * BNg * BSP)   /* 61440 B */

// ===========================================================================
// Variant 1: A fp32 (optionally PReLU), used for GEMM1 only (FUSED epilogue).
// ===========================================================================
__global__ __launch_bounds__(256, 2)
void gemm_mma_fused1(const float* __restrict__ A, const float* __restrict__ B,
                     float* __restrict__ C, float* __restrict__ C2,
                     int M, int K, int P, const float* __restrict__ prelu_a,
                     const float* __restrict__ emb1, const float* __restrict__ emb2)
{
    extern __shared__ uint32_t smem[];
    uint32_t* AH = smem;
    uint32_t* AL = smem + 2 * BMg * ASP;
    uint32_t* BH = smem + 4 * BMg * ASP;
    uint32_t* BL = smem + 4 * BMg * ASP + 2 * BNg * BSP;

    const int tid  = threadIdx.x;
    const int lane = tid & 31;
    const int w    = tid >> 5;
    const int wm   = (w & 3) * 32;
    const int wn   = (w >> 2) * 32;
    const int g    = lane >> 2;
    const int tg   = lane & 3;
    const int m0   = blockIdx.y * BMg;
    const int p0   = blockIdx.x * BNg;

    const float alpha = __ldg(prelu_a);

    int arow[4], ac4[4]; bool apred[4];
#pragma unroll
    for (int i = 0; i < 4; ++i) {
        int f4 = tid + i * 256;
        arow[i] = f4 >> 3; ac4[i] = f4 & 7;
        apred[i] = (m0 + arow[i]) < M;
    }
    int brow[2], bc4[2]; bool bpred[2];
#pragma unroll
    for (int i = 0; i < 2; ++i) {
        int f4 = tid + i * 256;
        brow[i] = f4 >> 3; bc4[i] = f4 & 7;
        bpred[i] = (p0 + brow[i]) < P;
    }

    const int a_row = lane & 15;
    const int a_kp0 = (lane >> 4) * 4;
    const int b_row = ((lane >> 4) & 1) * 8 + (lane & 7);
    const int b_kp0 = ((lane >> 3) & 1) * 4;

    float acc[2][4][4];
#pragma unroll
    for (int mt = 0; mt < 2; ++mt)
#pragma unroll
        for (int nt = 0; nt < 4; ++nt)
#pragma unroll
            for (int i = 0; i < 4; ++i) acc[mt][nt][i] = 0.0f;

    float4 pa[4], pb[2];

#pragma unroll
    for (int i = 0; i < 4; ++i)
        pa[i] = apred[i] ? __ldg((const float4*)(A + (size_t)(m0 + arow[i]) * K + ac4[i] * 4))
                         : make_float4(0.f, 0.f, 0.f, 0.f);
#pragma unroll
    for (int i = 0; i < 2; ++i)
        pb[i] = bpred[i] ? __ldg((const float4*)(B + (size_t)(p0 + brow[i]) * K + bc4[i] * 4))
                         : make_float4(0.f, 0.f, 0.f, 0.f);
    {
#pragma unroll
        for (int i = 0; i < 4; ++i) {
            float4 v = pa[i];
            v.x = v.x > 0.f ? v.x : alpha * v.x;
            v.y = v.y > 0.f ? v.y : alpha * v.y;
            v.z = v.z > 0.f ? v.z : alpha * v.z;
            v.w = v.w > 0.f ? v.w : alpha * v.w;
            uint32_t h0, h1, l0, l1; cvt4(v, h0, h1, l0, l1);
            int base = arow[i] * ASP + ac4[i] * 2;
            AH[base] = h0; AH[base + 1] = h1;
            AL[base] = l0; AL[base + 1] = l1;
        }
#pragma unroll
        for (int i = 0; i < 2; ++i) {
            uint32_t h0, h1, l0, l1; cvt4(pb[i], h0, h1, l0, l1);
            int base = brow[i] * BSP + bc4[i] * 2;
            BH[base] = h0; BH[base + 1] = h1;
            BL[base] = l0; BL[base + 1] = l1;
        }
    }
    __syncthreads();

    const int niter = K / 32;
    for (int it = 0; it < niter; ++it) {
        const int cur = it & 1;
        const bool has_next = (it + 1) < niter;
        const int knext = (it + 1) * 32;

        if (has_next) {
#pragma unroll
            for (int i = 0; i < 4; ++i)
                pa[i] = apred[i] ? __ldg((const float4*)(A + (size_t)(m0 + arow[i]) * K + knext + ac4[i] * 4))
                                 : make_float4(0.f, 0.f, 0.f, 0.f);
#pragma unroll
            for (int i = 0; i < 2; ++i)
                pb[i] = bpred[i] ? __ldg((const float4*)(B + (size_t)(p0 + brow[i]) * K + knext + bc4[i] * 4))
                                 : make_float4(0.f, 0.f, 0.f, 0.f);
        }

        const uint32_t* cAH = AH + cur * BMg * ASP;
        const uint32_t* cAL = AL + cur * BMg * ASP;
        const uint32_t* cBH = BH + cur * BNg * BSP;
        const uint32_t* cBL = BL + cur * BNg * BSP;
#pragma unroll
        for (int ks = 0; ks < 2; ++ks) {
            uint32_t ah[2][4], al[2][4], bh[2][4], bl[2][4];
            int akp = ks * 8 + a_kp0;
            int bkp = ks * 8 + b_kp0;
#pragma unroll
            for (int mt = 0; mt < 2; ++mt) {
                int r = wm + mt * 16 + a_row;
                ldsm4(ah[mt], &cAH[r * ASP + akp]);
                ldsm4(al[mt], &cAL[r * ASP + akp]);
            }
#pragma unroll
            for (int p = 0; p < 2; ++p) {
                int n = wn + p * 16 + b_row;
                ldsm4(bh[p], &cBH[n * BSP + bkp]);
                ldsm4(bl[p], &cBL[n * BSP + bkp]);
            }
#pragma unroll
            for (int p = 0; p < 2; ++p) {
#pragma unroll
                for (int half = 0; half < 2; ++half) {
                    int nt = p * 2 + half;
                    uint32_t b0  = bh[p][half * 2], b1  = bh[p][half * 2 + 1];
                    uint32_t lb0 = bl[p][half * 2], lb1 = bl[p][half * 2 + 1];
#pragma unroll
                    for (int mt = 0; mt < 2; ++mt) {
                        mma16816(acc[mt][nt], ah[mt], b0, b1);
                        mma16816(acc[mt][nt], al[mt], b0, b1);
                        mma16816(acc[mt][nt], ah[mt], lb0, lb1);
                    }
                }
            }
        }

        if (has_next) {
            uint32_t* nAH = AH + (cur ^ 1) * BMg * ASP;
            uint32_t* nAL = AL + (cur ^ 1) * BMg * ASP;
            uint32_t* nBH = BH + (cur ^ 1) * BNg * BSP;
            uint32_t* nBL = BL + (cur ^ 1) * BNg * BSP;
#pragma unroll
            for (int i = 0; i < 4; ++i) {
                float4 v = pa[i];
                v.x = v.x > 0.f ? v.x : alpha * v.x;
                v.y = v.y > 0.f ? v.y : alpha * v.y;
                v.z = v.z > 0.f ? v.z : alpha * v.z;
                v.w = v.w > 0.f ? v.w : alpha * v.w;
                uint32_t h0, h1, l0, l1; cvt4(v, h0, h1, l0, l1);
                int base = arow[i] * ASP + ac4[i] * 2;
                nAH[base] = h0; nAH[base + 1] = h1;
                nAL[base] = l0; nAL[base + 1] = l1;
            }
#pragma unroll
            for (int i = 0; i < 2; ++i) {
                uint32_t h0, h1, l0, l1; cvt4(pb[i], h0, h1, l0, l1);
                int base = brow[i] * BSP + bc4[i] * 2;
                nBH[base] = h0; nBH[base + 1] = h1;
                nBL[base] = l0; nBL[base + 1] = l1;
            }
        }
        __syncthreads();
    }

    // Epilogue: h = mask(v); aggr = h + emb1[4]+emb2[0]
#pragma unroll
    for (int mt = 0; mt < 2; ++mt) {
#pragma unroll
        for (int nt = 0; nt < 4; ++nt) {
            int row0 = m0 + wm + mt * 16 + g;
            int col  = p0 + wn + nt * 8 + tg * 2;
            float ec0 = __ldg(emb1 + 4 * D_IN + col) + __ldg(emb2 + col);
            float ec1 = __ldg(emb1 + 4 * D_IN + col + 1) + __ldg(emb2 + col + 1);
#pragma unroll
            for (int h = 0; h < 2; ++h) {
                int row = row0 + h * 8;
                if (row >= M) continue;
                float v0 = acc[mt][nt][h * 2 + 0];
                float v1 = acc[mt][nt][h * 2 + 1];
                bool masked = (__ldg(&g_maskbits[row >> 5]) >> (row & 31)) & 1u;
                if (masked) { v0 = 0.f; v1 = 0.f; }
                C[(size_t)row * P + col]      = v0;
                C[(size_t)row * P + col + 1]  = v1;
                C2[(size_t)row * P + col]     = v0 + ec0;
                C2[(size_t)row * P + col + 1] = v1 + ec1;
            }
        }
    }
}

// ===========================================================================
// Variant 2: A pre-packed hi/lo bf16x2 planes (no convert in mainloop).
// B fp32 with in-kernel split. Output fp32 (PACK_OUT=0) or packed (PACK_OUT=1).
// ===========================================================================
template<bool RELU_OUT, bool PACK_OUT>
__global__ __launch_bounds__(256, 2)
void gemm_mma_packed(const uint32_t* __restrict__ Ahi, const uint32_t* __restrict__ Alo,
                     const float* __restrict__ B, const float* __restrict__ bias,
                     float* __restrict__ C, uint32_t* __restrict__ Chi,
                     uint32_t* __restrict__ Clo,
                     int M, int K, int P)
{
    extern __shared__ uint32_t smem[];
    uint32_t* AH = smem;
    uint32_t* AL = smem + 2 * BMg * ASP;
    uint32_t* BH = smem + 4 * BMg * ASP;
    uint32_t* BL = smem + 4 * BMg * ASP + 2 * BNg * BSP;

    const int tid  = threadIdx.x;
    const int lane = tid & 31;
    const int w    = tid >> 5;
    const int wm   = (w & 3) * 32;
    const int wn   = (w >> 2) * 32;
    const int g    = lane >> 2;
    const int tg   = lane & 3;
    const int m0   = blockIdx.y * BMg;
    const int p0   = blockIdx.x * BNg;
    const int KW   = K / 2;   // words per row in packed planes

    // A loads: 512 uint4 per plane per tile -> 2 per thread per plane
    int prow[2], pw4[2]; bool ppred[2];
#pragma unroll
    for (int i = 0; i < 2; ++i) {
        int idx = tid + i * 256;
        prow[i] = idx >> 2; pw4[i] = idx & 3;   // 4 uint4 per row (16 words)
        ppred[i] = (m0 + prow[i]) < M;
    }
    int brow[2], bc4[2]; bool bpred[2];
#pragma unroll
    for (int i = 0; i < 2; ++i) {
        int f4 = tid + i * 256;
        brow[i] = f4 >> 3; bc4[i] = f4 & 7;
        bpred[i] = (p0 + brow[i]) < P;
    }

    const int a_row = lane & 15;
    const int a_kp0 = (lane >> 4) * 4;
    const int b_row = ((lane >> 4) & 1) * 8 + (lane & 7);
    const int b_kp0 = ((lane >> 3) & 1) * 4;

    float acc[2][4][4];
#pragma unroll
    for (int mt = 0; mt < 2; ++mt)
#pragma unroll
        for (int nt = 0; nt < 4; ++nt)
#pragma unroll
            for (int i = 0; i < 4; ++i) acc[mt][nt][i] = 0.0f;

    uint4 pah[2], pal[2];
    float4 pb[2];
    const uint4 z4 = make_uint4(0u, 0u, 0u, 0u);

#pragma unroll
    for (int i = 0; i < 2; ++i) {
        size_t off = (size_t)(m0 + prow[i]) * KW + pw4[i] * 4;
        pah[i] = ppred[i] ? __ldg((const uint4*)(Ahi + off)) : z4;
        pal[i] = ppred[i] ? __ldg((const uint4*)(Alo + off)) : z4;
    }
#pragma unroll
    for (int i = 0; i < 2; ++i)
        pb[i] = bpred[i] ? __ldg((const float4*)(B + (size_t)(p0 + brow[i]) * K + bc4[i] * 4))
                         : make_float4(0.f, 0.f, 0.f, 0.f);
    {
#pragma unroll
        for (int i = 0; i < 2; ++i) {
            int base = prow[i] * ASP + pw4[i] * 4;
            *(uint4*)&AH[base] = pah[i];
            *(uint4*)&AL[base] = pal[i];
        }
#pragma unroll
        for (int i = 0; i < 2; ++i) {
            uint32_t h0, h1, l0, l1; cvt4(pb[i], h0, h1, l0, l1);
            int base = brow[i] * BSP + bc4[i] * 2;
            BH[base] = h0; BH[base + 1] = h1;
            BL[base] = l0; BL[base + 1] = l1;
        }
    }
    __syncthreads();

    const int niter = K / 32;
    for (int it = 0; it < niter; ++it) {
        const int cur = it & 1;
        const bool has_next = (it + 1) < niter;
        const int kwnext = (it + 1) * 16;   // words

        if (has_next) {
#pragma unroll
            for (int i = 0; i < 2; ++i) {
                size_t off = (size_t)(m0 + prow[i]) * KW + kwnext + pw4[i] * 4;
                pah[i] = ppred[i] ? __ldg((const uint4*)(Ahi + off)) : z4;
                pal[i] = ppred[i] ? __ldg((const uint4*)(Alo + off)) : z4;
            }
#pragma unroll
            for (int i = 0; i < 2; ++i)
                pb[i] = bpred[i] ? __ldg((const float4*)(B + (size_t)(p0 + brow[i]) * K + (it + 1) * 32 + bc4[i] * 4))
                                 : make_float4(0.f, 0.f, 0.f, 0.f);
        }

        const uint32_t* cAH = AH + cur * BMg * ASP;
        const uint32_t* cAL = AL + cur * BMg * ASP;
        const uint32_t* cBH = BH + cur * BNg * BSP;
        const uint32_t* cBL = BL + cur * BNg * BSP;
#pragma unroll
        for (int ks = 0; ks < 2; ++ks) {
            uint32_t ah[2][4], al[2][4], bh[2][4], bl[2][4];
            int akp = ks * 8 + a_kp0;
            int bkp = ks * 8 + b_kp0;
#pragma unroll
            for (int mt = 0; mt < 2; ++mt) {
                int r = wm + mt * 16 + a_row;
                ldsm4(ah[mt], &cAH[r * ASP + akp]);
                ldsm4(al[mt], &cAL[r * ASP + akp]);
            }
#pragma unroll
            for (int p = 0; p < 2; ++p) {
                int n = wn + p * 16 + b_row;
                ldsm4(bh[p], &cBH[n * BSP + bkp]);
                ldsm4(bl[p], &cBL[n * BSP + bkp]);
            }
#pragma unroll
            for (int p = 0; p < 2; ++p) {
#pragma unroll
                for (int half = 0; half < 2; ++half) {
                    int nt = p * 2 + half;
                    uint32_t b0  = bh[p][half * 2], b1  = bh[p][half * 2 + 1];
                    uint32_t lb0 = bl[p][half * 2], lb1 = bl[p][half * 2 + 1];
#pragma unroll
                    for (int mt = 0; mt < 2; ++mt) {
                        mma16816(acc[mt][nt], ah[mt], b0, b1);
                        mma16816(acc[mt][nt], al[mt], b0, b1);
                        mma16816(acc[mt][nt], ah[mt], lb0, lb1);
                    }
                }
            }
        }

        if (has_next) {
            uint32_t* nAH = AH + (cur ^ 1) * BMg * ASP;
            uint32_t* nAL = AL + (cur ^ 1) * BMg * ASP;
            uint32_t* nBH = BH + (cur ^ 1) * BNg * BSP;
            uint32_t* nBL = BL + (cur ^ 1) * BNg * BSP;
#pragma unroll
            for (int i = 0; i < 2; ++i) {
                int base = prow[i] * ASP + pw4[i] * 4;
                *(uint4*)&nAH[base] = pah[i];
                *(uint4*)&nAL[base] = pal[i];
            }
#pragma unroll
            for (int i = 0; i < 2; ++i) {
                uint32_t h0, h1, l0, l1; cvt4(pb[i], h0, h1, l0, l1);
                int base = brow[i] * BSP + bc4[i] * 2;
                nBH[base] = h0; nBH[base + 1] = h1;
                nBL[base] = l0; nBL[base + 1] = l1;
            }
        }
        __syncthreads();
    }

    // Epilogue
#pragma unroll
    for (int mt = 0; mt < 2; ++mt) {
#pragma unroll
        for (int nt = 0; nt < 4; ++nt) {
            int row0 = m0 + wm + mt * 16 + g;
            int col  = p0 + wn + nt * 8 + tg * 2;
            float b0 = 0.f, b1 = 0.f;
            if (col < P)     b0 = __ldg(bias + col);
            if (col + 1 < P) b1 = __ldg(bias + col + 1);
#pragma unroll
            for (int h = 0; h < 2; ++h) {
                int row = row0 + h * 8;
                if (row >= M) continue;
                float v0 = acc[mt][nt][h * 2 + 0] + b0;
                float v1 = acc[mt][nt][h * 2 + 1] + b1;
                if (RELU_OUT) { v0 = fmaxf(v0, 0.f); v1 = fmaxf(v1, 0.f); }
                if (PACK_OUT) {
                    // P even; col = even. Write one hi word + one lo word.
                    __nv_bfloat16 h0, l0, h1, l1;
                    split_bf16(v0, h0, l0); split_bf16(v1, h1, l1);
                    __nv_bfloat162 hw = __nv_bfloat162(h0, h1);
                    __nv_bfloat162 lw = __nv_bfloat162(l0, l1);
                    Chi[(size_t)row * (P / 2) + (col >> 1)] = *(uint32_t*)&hw;
                    Clo[(size_t)row * (P / 2) + (col >> 1)] = *(uint32_t*)&lw;
                } else {
                    if (col < P)     C[(size_t)row * P + col]     = v0;
                    if (col + 1 < P) C[(size_t)row * P + col + 1] = v1;
                }
            }
        }
    }
}

// ---------------------------------------------------------------------------
// Build mask bitmap. Single block: zero then set.
// ---------------------------------------------------------------------------
__global__ void maskbits_kernel(const int* __restrict__ mi, int NM)
{
    const int W = (N_NODES + 31) / 32;
    for (int i = threadIdx.x; i < W; i += blockDim.x) g_maskbits[i] = 0u;
    __syncthreads();
    for (int i = threadIdx.x; i < NM; i += blockDim.x) {
        int r = __ldg(mi + i);
        if (r >= 0 && r < N_NODES)
            atomicOr(&g_maskbits[r >> 5], 1u << (r & 31));
    }
}

// ---------------------------------------------------------------------------
// Pack aggr fp32 -> hi/lo bf16x2 planes. One thread per float4 (2 words).
// ---------------------------------------------------------------------------
__global__ void pack_kernel(const float* __restrict__ src,
                            uint32_t* __restrict__ hi, uint32_t* __restrict__ lo,
                            int nf4)
{
    int t = blockIdx.x * blockDim.x + threadIdx.x;
    if (t >= nf4) return;
    float4 v = *(const float4*)(src + (size_t)t * 4);
    uint32_t h0, h1, l0, l1; cvt4(v, h0, h1, l0, l1);
    hi[(size_t)t * 2]     = h0;
    hi[(size_t)t * 2 + 1] = h1;
    lo[(size_t)t * 2]     = l0;
    lo[(size_t)t * 2 + 1] = l1;
}

// ---------------------------------------------------------------------------
// Edge scatter: aggr[dst] += h[src] + emb1[et] + emb2[ed].
// One warp per FOUR edges, software-pipelined gathers, vector red.add.
// ---------------------------------------------------------------------------
__global__ void edge_kernel(const int* __restrict__ ei,
                            const int* __restrict__ ea,
                            const float* __restrict__ emb1,
                            const float* __restrict__ emb2, int E)
{
    int w = (blockIdx.x * blockDim.x + threadIdx.x) >> 5;
    int lane = threadIdx.x & 31;
    int c = lane * 4;
    int base = w * 4;
    if (base >= E) return;

    int src[4], dst[4], et[4], ed[4];
#pragma unroll
    for (int j = 0; j < 4; ++j) {
        int e = base + j;
        if (e < E) {
            src[j] = __ldg(ei + e);
            dst[j] = __ldg(ei + E + e);
            et[j]  = __ldg(ea + 2 * e);
            ed[j]  = __ldg(ea + 2 * e + 1);
        } else { src[j] = 0; dst[j] = -1; et[j] = 0; ed[j] = 0; }
    }
    float4 hv[4], e1[4], e2[4];
#pragma unroll
    for (int j = 0; j < 4; ++j) {
        hv[j] = *(const float4*)(g_h + (size_t)src[j] * D_IN + c);
        e1[j] = __ldg((const float4*)(emb1 + (size_t)et[j] * D_IN + c));
        e2[j] = __ldg((const float4*)(emb2 + (size_t)ed[j] * D_IN + c));
    }
#pragma unroll
    for (int j = 0; j < 4; ++j) {
        if (dst[j] < 0) continue;
        float m0 = hv[j].x + e1[j].x + e2[j].x;
        float m1 = hv[j].y + e1[j].y + e2[j].y;
        float m2 = hv[j].z + e1[j].z + e2[j].z;
        float m3 = hv[j].w + e1[j].w + e2[j].w;
        float* p = g_aggr + (size_t)dst[j] * D_IN + c;
        asm volatile("red.global.add.v4.f32 [%0], {%1, %2, %3, %4};"
                     :: "l"(p), "f"(m0), "f"(m1), "f"(m2), "f"(m3)
                     : "memory");
    }
}

// ---------------------------------------------------------------------------
extern "C" void kernel_launch(void* const* d_in, const int* in_sizes, int n_in,
                              void* d_out, int out_size)
{
    const float* x       = (const float*)d_in[0];
    const int*   ei      = (const int*)d_in[1];
    const int*   ea      = (const int*)d_in[2];
    const int*   mi      = (const int*)d_in[3];
    const float* prelu_a = (const float*)d_in[4];
    const float* W_enc   = (const float*)d_in[5];
    const float* emb1    = (const float*)d_in[6];
    const float* emb2    = (const float*)d_in[7];
    const float* W1      = (const float*)d_in[8];
    const float* b1      = (const float*)d_in[9];
    const float* W2      = (const float*)d_in[10];
    const float* b2      = (const float*)d_in[11];
    float*       out     = (float*)d_out;

    const int N  = in_sizes[0] / D_IN;
    const int E  = in_sizes[1] / 2;
    const int NM = in_sizes[3];

    const int SMEM_BYTES = SMEM_WORDS * 4;   // 61440

    // Idempotent, called every invocation (no static guards -- harness rule)
    cudaFuncSetAttribute(gemm_mma_fused1,
                         cudaFuncAttributeMaxDynamicSharedMemorySize, SMEM_BYTES);
    cudaFuncSetAttribute(gemm_mma_packed<true, true>,
                         cudaFuncAttributeMaxDynamicSharedMemorySize, SMEM_BYTES);
    cudaFuncSetAttribute(gemm_mma_packed<false, false>,
                         cudaFuncAttributeMaxDynamicSharedMemorySize, SMEM_BYTES);

    float *h_ptr, *aggr_ptr;
    uint32_t *ahi_ptr, *alo_ptr, *hidh_ptr, *hidl_ptr;
    cudaGetSymbolAddress((void**)&h_ptr, g_h);
    cudaGetSymbolAddress((void**)&aggr_ptr, g_aggr);
    cudaGetSymbolAddress((void**)&ahi_ptr, g_Ahi);
    cudaGetSymbolAddress((void**)&alo_ptr, g_Alo);
    cudaGetSymbolAddress((void**)&hidh_ptr, g_hidh);
    cudaGetSymbolAddress((void**)&hidl_ptr, g_hidl);

    // 0) mask bitmap
    maskbits_kernel<<<1, 1024>>>(mi, NM);

    // 1) h = mask(prelu(x) @ W_enc^T); aggr = h + emb1[4]+emb2[0]   (fused)
    {
        dim3 grid((D_IN + BNg - 1) / BNg, (N + BMg - 1) / BMg);
        gemm_mma_fused1<<<grid, 256, SMEM_BYTES>>>(
            x, W_enc, h_ptr, aggr_ptr, N, D_IN, D_IN, prelu_a, emb1, emb2);
    }
    // 2) edge scatter-add (4 edges per warp)
    {
        int warps = (E + 3) / 4;
        long long threads = (long long)warps * 32;
        edge_kernel<<<(int)((threads + 255) / 256), 256>>>(ei, ea, emb1, emb2, E);
    }
    // 3) pack aggr -> hi/lo planes
    {
        int nf4 = N * (D_IN / 4);
        pack_kernel<<<(nf4 + 255) / 256, 256>>>(aggr_ptr, ahi_ptr, alo_ptr, nf4);
    }
    // 4) hid = relu(aggr @ W1^T + b1), packed in/out
    {
        dim3 grid((D_FF + BNg - 1) / BNg, (N + BMg - 1) / BMg);
        gemm_mma_packed<true, true><<<grid, 256, SMEM_BYTES>>>(
            ahi_ptr, alo_ptr, W1, b1, nullptr, hidh_ptr, hidl_ptr, N, D_IN, D_FF);
    }
    // 5) out = hid @ W2^T + b2, packed A, fp32 out
    {
        dim3 grid((D_OUT + BNg - 1) / BNg, (N + BMg - 1) / BMg);
        gemm_mma_packed<false, false><<<grid, 256, SMEM_BYTES>>>(
            hidh_ptr, hidl_ptr, W2, b2, out, nullptr, nullptr, N, D_FF, D_OUT);
    }
}